// round 14
// baseline (speedup 1.0000x reference)
#include <cuda_runtime.h>

#define IN_SZ   448
#define OUT_SZ  224
#define BATCH   64
#define PLANE   (IN_SZ * IN_SZ)
#define GRIDSZ  (14 * BATCH)          // 896 blocks: one (image, row-band) each

// Packed coefficients: (a0, a1, c0_bits, c1_bits) and (b0, b1, r0_bits, r1_bits)
__device__ float4 g_col[BATCH * OUT_SZ];
__device__ float4 g_row[BATCH * OUT_SZ];

__device__ __forceinline__ float sig10(float z) {
    return 1.0f / (1.0f + __expf(-10.0f * z));
}

// ---------------------------------------------------------------------------
// Prologue: packed coefficients. grid=64, block=224. Tiny.
// ---------------------------------------------------------------------------
__global__ void racnn_coef_kernel(const float* __restrict__ locs) {
    const int b = blockIdx.x;
    const int j = threadIdx.x;            // 0..223

    float tx = locs[b * 3 + 0];
    float ty = locs[b * 3 + 1];
    float tl = locs[b * 3 + 2];

    tl = fmaxf(tl, 448.0f / 3.0f);
    tx = fminf(fmaxf(tx, tl), 448.0f - tl);
    ty = fminf(fmaxf(ty, tl), 448.0f - tl);

    const float w_off = fmaxf(floorf(tx - tl), 0.0f);
    const float h_off = fmaxf(floorf(ty - tl), 0.0f);
    const float w_end = fminf(floorf(tx + tl), 448.0f);
    const float h_end = fminf(floorf(ty + tl), 448.0f);

    const float fj = (float)j;

    // row side (w axis)
    {
        const float step = (w_end - w_off - 1.0f) * (1.0f / 223.0f);
        const float src  = w_off + fj * step;
        const float r0f  = fminf(fmaxf(floorf(src), 0.0f), 447.0f);
        const float wr   = src - r0f;
        const int   r0   = (int)r0f;
        const int   r1   = min(r0 + 1, IN_SZ - 1);
        const float mr0  = sig10(r0f - w_off) - sig10(r0f - w_end);
        const float mr1  = sig10((float)r1 - w_off) - sig10((float)r1 - w_end);
        g_row[b * OUT_SZ + j] = make_float4((1.0f - wr) * mr0, wr * mr1,
                                            __int_as_float(r0), __int_as_float(r1));
    }

    // column side (h axis)
    {
        const float step = (h_end - h_off - 1.0f) * (1.0f / 223.0f);
        const float src  = h_off + fj * step;
        const float c0f  = fminf(fmaxf(floorf(src), 0.0f), 447.0f);
        const float wc   = src - c0f;
        const int   c0   = (int)c0f;
        const int   c1   = min(c0 + 1, IN_SZ - 1);
        const float mc0  = sig10(c0f - h_off) - sig10(c0f - h_end);
        const float mc1  = sig10((float)c1 - h_off) - sig10((float)c1 - h_end);
        g_col[b * OUT_SZ + j] = make_float4((1.0f - wc) * mc0, wc * mc1,
                                            __int_as_float(c0), __int_as_float(c1));
    }
}

// ---------------------------------------------------------------------------
// Main gather. Block = one (image b, 16-row band); iterates 7 column tiles.
// Row coefficients hoisted out of the tile loop (shared by all 7 tiles).
// Thread/iter = 1 col x 2 rows x 3 ch = 6 px, 24 independent gather LDGs
// + 1 packed coef LDG.128 + 6 streaming STG.32. No barriers.
// ---------------------------------------------------------------------------
__global__ __launch_bounds__(256) void racnn_gather_kernel(
    const float* __restrict__ img, float* __restrict__ out)
{
    const int b  = blockIdx.x / 14;
    const int ty = blockIdx.x - b * 14;
    const int jr = ty * 16 + threadIdx.y * 2;      // first of this thread's 2 rows

    // ---- hoisted row coefficients (warp-uniform) ----
    const float4 rw0 = __ldg(&g_row[b * OUT_SZ + jr]);
    const float4 rw1 = __ldg(&g_row[b * OUT_SZ + jr + 1]);
    const float b00 = rw0.x, b01 = rw0.y;
    const float b10 = rw1.x, b11 = rw1.y;
    const int   r00 = __float_as_int(rw0.z), r01 = __float_as_int(rw0.w);
    const int   r10 = __float_as_int(rw1.z), r11 = __float_as_int(rw1.w);

    const float* base = img + (size_t)b * 3 * PLANE;
    const float* row_p0 = base + r00 * IN_SZ;
    const float* row_p1 = base + r01 * IN_SZ;
    const float* row_q0 = base + r10 * IN_SZ;
    const float* row_q1 = base + r11 * IN_SZ;

    const float4* ccp  = &g_col[b * OUT_SZ + threadIdx.x];
    float* obase = out + (size_t)b * 3 * OUT_SZ * OUT_SZ + jr * OUT_SZ + threadIdx.x;

    #pragma unroll
    for (int t = 0; t < 7; t++) {
        const float4 cc = __ldg(ccp + t * 32);
        const float a0 = cc.x, a1 = cc.y;
        const int   c0 = __float_as_int(cc.z);
        const int   c1 = __float_as_int(cc.w);

        float v[3][8];
        #pragma unroll
        for (int ch = 0; ch < 3; ch++) {
            const int o = ch * PLANE;
            v[ch][0] = __ldg(row_p0 + o + c0);
            v[ch][1] = __ldg(row_p0 + o + c1);
            v[ch][2] = __ldg(row_p1 + o + c0);
            v[ch][3] = __ldg(row_p1 + o + c1);
            v[ch][4] = __ldg(row_q0 + o + c0);
            v[ch][5] = __ldg(row_q0 + o + c1);
            v[ch][6] = __ldg(row_q1 + o + c0);
            v[ch][7] = __ldg(row_q1 + o + c1);
        }

        float* op = obase + t * 32;
        #pragma unroll
        for (int ch = 0; ch < 3; ch++) {
            const float t0 = fmaf(a1, v[ch][1], a0 * v[ch][0]);
            const float u0 = fmaf(a1, v[ch][3], a0 * v[ch][2]);
            const float t1 = fmaf(a1, v[ch][5], a0 * v[ch][4]);
            const float u1 = fmaf(a1, v[ch][7], a0 * v[ch][6]);
            __stcs(op + (size_t)ch * OUT_SZ * OUT_SZ,
                   fmaf(b01, u0, b00 * t0));
            __stcs(op + (size_t)ch * OUT_SZ * OUT_SZ + OUT_SZ,
                   fmaf(b11, u1, b10 * t1));
        }
    }
}

// ---------------------------------------------------------------------------
extern "C" void kernel_launch(void* const* d_in, const int* in_sizes, int n_in,
                              void* d_out, int out_size)
{
    const float* images = (const float*)d_in[0];
    const float* locs   = (const float*)d_in[1];
    if (n_in >= 2 && in_sizes[0] == BATCH * 3) {
        locs   = (const float*)d_in[0];
        images = (const float*)d_in[1];
    }
    float* out = (float*)d_out;

    racnn_coef_kernel<<<BATCH, OUT_SZ>>>(locs);

    dim3 block(32, 8, 1);                 // 256 threads
    racnn_gather_kernel<<<GRIDSZ, block>>>(images, out);
}

// round 15
// speedup vs baseline: 1.1454x; 1.1454x over previous
#include <cuda_runtime.h>

#define IN_SZ   448
#define OUT_SZ  224
#define BATCH   64
#define PLANE   (IN_SZ * IN_SZ)
#define GRIDSZ  (14 * BATCH)          // 896 blocks: one (image, 16-row band)

__device__ __forceinline__ float sig10(float z) {
    return 1.0f / (1.0f + __expf(-10.0f * z));
}

// Single fused kernel. Block = (image b, 16-row band), 256 threads.
// Phase 0: 240 threads compute this block's coefficients into smem.
// Tile loop: R12's proven gather body (rolled, coefs via LDS).
__global__ __launch_bounds__(256) void racnn_kernel(
    const float* __restrict__ img, const float* __restrict__ locs,
    float* __restrict__ out)
{
    __shared__ float2 sA[OUT_SZ];   // col (a0, a1)
    __shared__ int2   sC[OUT_SZ];   // col (c0, c1)
    __shared__ float2 sB[16];       // row (b0, b1)
    __shared__ int2   sR[16];       // row (r0, r1)

    const int b   = blockIdx.x / 14;
    const int ty  = blockIdx.x - b * 14;
    const int tid = threadIdx.y * 32 + threadIdx.x;

    // ---------------- Phase 0: coefficients (240 threads) ----------------
    if (tid < OUT_SZ + 16) {
        float tx = __ldg(&locs[b * 3 + 0]);
        float tyy = __ldg(&locs[b * 3 + 1]);
        float tl = __ldg(&locs[b * 3 + 2]);

        tl  = fmaxf(tl, 448.0f / 3.0f);
        tx  = fminf(fmaxf(tx, tl), 448.0f - tl);
        tyy = fminf(fmaxf(tyy, tl), 448.0f - tl);

        const float w_off = fmaxf(floorf(tx - tl), 0.0f);
        const float h_off = fmaxf(floorf(tyy - tl), 0.0f);
        const float w_end = fminf(floorf(tx + tl), 448.0f);
        const float h_end = fminf(floorf(tyy + tl), 448.0f);

        if (tid < OUT_SZ) {
            // column side (h axis), j = tid
            const float fj   = (float)tid;
            const float step = (h_end - h_off - 1.0f) * (1.0f / 223.0f);
            const float src  = h_off + fj * step;
            const float c0f  = fminf(fmaxf(floorf(src), 0.0f), 447.0f);
            const float wc   = src - c0f;
            const int   c0   = (int)c0f;
            const int   c1   = min(c0 + 1, IN_SZ - 1);
            const float mc0  = sig10(c0f - h_off) - sig10(c0f - h_end);
            const float mc1  = sig10((float)c1 - h_off) - sig10((float)c1 - h_end);
            sA[tid] = make_float2((1.0f - wc) * mc0, wc * mc1);
            sC[tid] = make_int2(c0, c1);
        } else {
            // row side (w axis), j = ty*16 + k
            const int   k    = tid - OUT_SZ;
            const float fj   = (float)(ty * 16 + k);
            const float step = (w_end - w_off - 1.0f) * (1.0f / 223.0f);
            const float src  = w_off + fj * step;
            const float r0f  = fminf(fmaxf(floorf(src), 0.0f), 447.0f);
            const float wr   = src - r0f;
            const int   r0   = (int)r0f;
            const int   r1   = min(r0 + 1, IN_SZ - 1);
            const float mr0  = sig10(r0f - w_off) - sig10(r0f - w_end);
            const float mr1  = sig10((float)r1 - w_off) - sig10((float)r1 - w_end);
            sB[k] = make_float2((1.0f - wr) * mr0, wr * mr1);
            sR[k] = make_int2(r0, r1);
        }
    }
    __syncthreads();

    // ---------------- Tile loop: R12 body, coefs from smem ----------------
    const int kband = threadIdx.y * 2;             // row pair within band
    const int jr    = ty * 16 + kband;

    #pragma unroll 1
    for (int t = 0; t < 7; t++) {
        const int jc = t * 32 + threadIdx.x;       // 0..223

        const float2 a = sA[jc];
        const int2   c = sC[jc];

        const int2   r0 = sR[kband];
        const int2   r1 = sR[kband + 1];
        const float2 b0 = sB[kband];
        const float2 b1 = sB[kband + 1];

        const float* base = img + (size_t)b * 3 * PLANE;

        const float* p00 = base + r0.x * IN_SZ + c.x;
        const float* p01 = base + r0.x * IN_SZ + c.y;
        const float* p10 = base + r0.y * IN_SZ + c.x;
        const float* p11 = base + r0.y * IN_SZ + c.y;
        const float* q00 = base + r1.x * IN_SZ + c.x;
        const float* q01 = base + r1.x * IN_SZ + c.y;
        const float* q10 = base + r1.y * IN_SZ + c.x;
        const float* q11 = base + r1.y * IN_SZ + c.y;

        float v[3][8];
        #pragma unroll
        for (int ch = 0; ch < 3; ch++) {
            const int o = ch * PLANE;
            v[ch][0] = __ldg(p00 + o);
            v[ch][1] = __ldg(p01 + o);
            v[ch][2] = __ldg(p10 + o);
            v[ch][3] = __ldg(p11 + o);
            v[ch][4] = __ldg(q00 + o);
            v[ch][5] = __ldg(q01 + o);
            v[ch][6] = __ldg(q10 + o);
            v[ch][7] = __ldg(q11 + o);
        }

        float* obase = out + (size_t)b * 3 * OUT_SZ * OUT_SZ + jr * OUT_SZ + jc;

        #pragma unroll
        for (int ch = 0; ch < 3; ch++) {
            const float t0 = fmaf(a.y, v[ch][1], a.x * v[ch][0]);
            const float u0 = fmaf(a.y, v[ch][3], a.x * v[ch][2]);
            const float t1 = fmaf(a.y, v[ch][5], a.x * v[ch][4]);
            const float u1 = fmaf(a.y, v[ch][7], a.x * v[ch][6]);
            float* op = obase + (size_t)ch * OUT_SZ * OUT_SZ;
            __stcs(op,          fmaf(b0.y, u0, b0.x * t0));
            __stcs(op + OUT_SZ, fmaf(b1.y, u1, b1.x * t1));
        }
    }
}

// ---------------------------------------------------------------------------
extern "C" void kernel_launch(void* const* d_in, const int* in_sizes, int n_in,
                              void* d_out, int out_size)
{
    const float* images = (const float*)d_in[0];
    const float* locs   = (const float*)d_in[1];
    if (n_in >= 2 && in_sizes[0] == BATCH * 3) {
        locs   = (const float*)d_in[0];
        images = (const float*)d_in[1];
    }
    float* out = (float*)d_out;

    dim3 block(32, 8, 1);                 // 256 threads
    racnn_kernel<<<GRIDSZ, block>>>(images, locs, out);
}